// round 4
// baseline (speedup 1.0000x reference)
#include <cuda_runtime.h>
#include <cuda_fp16.h>
#include <cstdint>

// Problem dims (fixed per reference)
#define NXK 1024
#define NFN 4096
#define MTOT 8192   // B*S

// Scratch (static device globals -- no allocation)
__device__ __half A_h[(size_t)MTOT * NXK];   // x in fp16, [M, K] K-contig
__device__ __half W_h[(size_t)NFN * NXK];    // weight transposed, [N, K] K-contig

// ---------------------------------------------------------------------------
// Helpers (sm_80-safe PTX only: cp.async, ldmatrix, mma.sync)
// ---------------------------------------------------------------------------
__device__ __forceinline__ uint32_t smem_u32(const void* p) {
    uint32_t a;
    asm("{ .reg .u64 t; cvta.to.shared.u64 t, %1; cvt.u32.u64 %0, t; }"
        : "=r"(a) : "l"(p));
    return a;
}

__device__ __forceinline__ void cp16(uint32_t dst, const void* src) {
    asm volatile("cp.async.cg.shared.global [%0], [%1], 16;" :: "r"(dst), "l"(src));
}
#define CP_COMMIT() asm volatile("cp.async.commit_group;" ::: "memory")
#define CP_WAIT1()  asm volatile("cp.async.wait_group 1;" ::: "memory")

__device__ __forceinline__ void ldsm_x4(uint32_t& r0, uint32_t& r1, uint32_t& r2,
                                        uint32_t& r3, uint32_t addr) {
    asm volatile("ldmatrix.sync.aligned.m8n8.x4.shared.b16 {%0,%1,%2,%3}, [%4];"
                 : "=r"(r0), "=r"(r1), "=r"(r2), "=r"(r3) : "r"(addr));
}

__device__ __forceinline__ void mma16816(float* c, const uint32_t* a, const uint32_t* b) {
    asm volatile(
        "mma.sync.aligned.m16n8k16.row.col.f32.f16.f16.f32 "
        "{%0,%1,%2,%3}, {%4,%5,%6,%7}, {%8,%9}, {%0,%1,%2,%3};"
        : "+f"(c[0]), "+f"(c[1]), "+f"(c[2]), "+f"(c[3])
        : "r"(a[0]), "r"(a[1]), "r"(a[2]), "r"(a[3]), "r"(b[0]), "r"(b[1]));
}

// ---------------------------------------------------------------------------
// Convert kernels
// ---------------------------------------------------------------------------
__global__ void conv_x_kernel(const float* __restrict__ x) {
    int i = blockIdx.x * blockDim.x + threadIdx.x;
    int stride = gridDim.x * blockDim.x;
    const float4* x4 = reinterpret_cast<const float4*>(x);
    __half2* a2 = reinterpret_cast<__half2*>(A_h);
    const int n4 = (MTOT * NXK) / 4;
    for (int idx = i; idx < n4; idx += stride) {
        float4 v = x4[idx];
        a2[idx * 2 + 0] = __floats2half2_rn(v.x, v.y);
        a2[idx * 2 + 1] = __floats2half2_rn(v.z, v.w);
    }
}

// Transpose W [K=1024, N=4096] f32 -> W_h [N, K] fp16 (exact: int8-valued)
__global__ void conv_w_kernel(const float* __restrict__ w) {
    __shared__ float tile[32][33];
    int n0 = blockIdx.x * 32;
    int k0 = blockIdx.y * 32;
    int tx = threadIdx.x, ty = threadIdx.y;  // (32, 8)
    #pragma unroll
    for (int i = 0; i < 32; i += 8)
        tile[ty + i][tx] = w[(size_t)(k0 + ty + i) * NFN + n0 + tx];
    __syncthreads();
    #pragma unroll
    for (int i = 0; i < 32; i += 8)
        W_h[(size_t)(n0 + ty + i) * NXK + k0 + tx] = __float2half_rn(tile[tx][ty + i]);
}

// ---------------------------------------------------------------------------
// GEMM: CTA 128x128, BK=64, 3-stage cp.async pipeline, mma.sync 16x8x16
// SMEM tiles stored with xor-swizzle on 16B chunks: chunk' = chunk ^ (row & 7)
// ---------------------------------------------------------------------------
static constexpr int BM = 128, BN = 128, BK = 64;
static constexpr int STAGES = 3;
static constexpr int KIT = NXK / BK;                 // 16
static constexpr uint32_t STG_BYTES = BM * BK * 2;   // 16384 per operand stage
static constexpr uint32_t SMEMSZ = STAGES * STG_BYTES * 2;  // 98304

__global__ void __launch_bounds__(256, 2) gemm_kernel(
    const float* __restrict__ scales,
    const float* __restrict__ bias,
    float* __restrict__ out)
{
    extern __shared__ __align__(128) char smem[];
    const uint32_t sA = smem_u32(smem);
    const uint32_t sB = sA + STAGES * STG_BYTES;

    const int tid  = threadIdx.x;
    const int lane = tid & 31;
    const int wid  = tid >> 5;            // 0..7
    const int wm   = wid & 3;             // 4 warps along M  (32 rows each)
    const int wn   = wid >> 2;            // 2 warps along N  (64 cols each)
    const int m0   = blockIdx.y * BM;
    const int n0   = blockIdx.x * BN;

    // loader mapping: 256 threads; chunk c = tid&7 (8 halves), row group r8 = tid>>3 (0..31)
    const int lc  = tid & 7;
    const int lr8 = tid >> 3;

    // fragment addressing constants
    const int q = lane >> 3;              // 0..3 (ldmatrix sub-matrix)
    const int e = lane & 7;

    float acc[2][8][4];
    #pragma unroll
    for (int mi = 0; mi < 2; mi++)
        #pragma unroll
        for (int ni = 0; ni < 8; ni++)
            #pragma unroll
            for (int t = 0; t < 4; t++) acc[mi][ni][t] = 0.f;

    auto issue = [&](int kt, int stage) {
        const uint32_t aBase = sA + stage * STG_BYTES;
        const uint32_t bBase = sB + stage * STG_BYTES;
        const int kh = kt * BK + lc * 8;  // k offset in halves
        #pragma unroll
        for (int p = 0; p < 4; p++) {
            int row = lr8 + p * 32;
            uint32_t sw = (uint32_t)(row * 8 + (lc ^ (row & 7))) * 16;
            cp16(aBase + sw, A_h + (size_t)(m0 + row) * NXK + kh);
            cp16(bBase + sw, W_h + (size_t)(n0 + row) * NXK + kh);
        }
    };

    // prologue: stages 0,1
    issue(0, 0); CP_COMMIT();
    issue(1, 1); CP_COMMIT();

    // per-lane ldmatrix row constants
    int rowA[2], rowB[4];
    #pragma unroll
    for (int mi = 0; mi < 2; mi++) rowA[mi] = wm * 32 + mi * 16 + (q & 1) * 8 + e;
    #pragma unroll
    for (int np = 0; np < 4; np++) rowB[np] = wn * 64 + np * 16 + (q >> 1) * 8 + e;
    const int chA = q >> 1;   // A chunk lsb within k16
    const int chB = q & 1;    // B chunk lsb within k16

    for (int kt = 0; kt < KIT; kt++) {
        CP_WAIT1();
        __syncthreads();   // stage kt ready; also fences previous compute before refill

        int nk = kt + STAGES - 1;
        if (nk < KIT) issue(nk, nk % STAGES);
        CP_COMMIT();

        const uint32_t aBase = sA + (kt % STAGES) * STG_BYTES;
        const uint32_t bBase = sB + (kt % STAGES) * STG_BYTES;

        #pragma unroll
        for (int kk = 0; kk < 4; kk++) {
            uint32_t af[2][4];
            #pragma unroll
            for (int mi = 0; mi < 2; mi++) {
                int r = rowA[mi];
                uint32_t addr = aBase + (uint32_t)(r * 8 + ((kk * 2 + chA) ^ (r & 7))) * 16;
                ldsm_x4(af[mi][0], af[mi][1], af[mi][2], af[mi][3], addr);
            }
            uint32_t bf[8][2];
            #pragma unroll
            for (int np = 0; np < 4; np++) {
                int r = rowB[np];
                uint32_t addr = bBase + (uint32_t)(r * 8 + ((kk * 2 + chB) ^ (r & 7))) * 16;
                ldsm_x4(bf[2 * np][0], bf[2 * np][1], bf[2 * np + 1][0], bf[2 * np + 1][1], addr);
            }
            #pragma unroll
            for (int mi = 0; mi < 2; mi++)
                #pragma unroll
                for (int ni = 0; ni < 8; ni++)
                    mma16816(acc[mi][ni], af[mi], bf[ni]);
        }
    }

    // epilogue: scale/bias + fp32 stores
    const int gro = lane >> 2;
    const int thc = (lane & 3) * 2;
    #pragma unroll
    for (int ni = 0; ni < 8; ni++) {
        int col = n0 + wn * 64 + ni * 8 + thc;
        float2 sc = *reinterpret_cast<const float2*>(scales + col);
        float2 bi = *reinterpret_cast<const float2*>(bias + col);
        #pragma unroll
        for (int mi = 0; mi < 2; mi++) {
            int r0 = m0 + wm * 32 + mi * 16 + gro;
            float2 v0, v1;
            v0.x = acc[mi][ni][0] * sc.x + bi.x;
            v0.y = acc[mi][ni][1] * sc.y + bi.y;
            v1.x = acc[mi][ni][2] * sc.x + bi.x;
            v1.y = acc[mi][ni][3] * sc.y + bi.y;
            *reinterpret_cast<float2*>(out + (size_t)r0 * NFN + col) = v0;
            *reinterpret_cast<float2*>(out + (size_t)(r0 + 8) * NFN + col) = v1;
        }
    }
}

// ---------------------------------------------------------------------------
// Host launch
// ---------------------------------------------------------------------------
extern "C" void kernel_launch(void* const* d_in, const int* in_sizes, int n_in,
                              void* d_out, int out_size) {
    const float* x    = (const float*)d_in[0];
    const float* qw   = (const float*)d_in[1];
    const float* ws   = (const float*)d_in[2];
    const float* bias = (const float*)d_in[3];
    float* out        = (float*)d_out;

    cudaFuncSetAttribute(gemm_kernel, cudaFuncAttributeMaxDynamicSharedMemorySize,
                         (int)SMEMSZ);

    conv_x_kernel<<<2048, 256>>>(x);
    conv_w_kernel<<<dim3(NFN / 32, NXK / 32), dim3(32, 8)>>>(qw);
    gemm_kernel<<<dim3(NFN / BN, MTOT / BM), 256, SMEMSZ>>>(ws, bias, out);
}